// round 10
// baseline (speedup 1.0000x reference)
#include <cuda_runtime.h>

#define NWIRES  12
#define DIM     4096
#define NLAYERS 4
#define NT      512
#define PER     8

__device__ __forceinline__ float2 cmul(float2 a, float2 b) {
    return make_float2(fmaf(a.x, b.x, -(a.y * b.y)),
                       fmaf(a.x, b.y,   a.y * b.x));
}
__device__ __forceinline__ float2 cfma(float2 a, float2 b, float2 c) {
    c.x = fmaf(a.x, b.x, fmaf(-a.y, b.y, c.x));
    c.y = fmaf(a.x, b.y, fmaf( a.y, b.x, c.y));
    return c;
}

// bank swizzle for 512-thread / 8-amp layout
__device__ __forceinline__ int saddr(int j) { return j ^ ((j >> 3) & 15); }

// h = g^{-1} (prefix-XOR) of the CNOT-chain permutation, then swizzle
__device__ __forceinline__ int haddr(int j) {
    j ^= j >> 1; j ^= j >> 2; j ^= j >> 4; j ^= j >> 8;
    return saddr(j);
}

// logical index owned by thread t, local slot v (3 bits), for round R
template <int R>
__device__ __forceinline__ int jidx(int t, int v) {
    if (R == 0) return (t << 3) | v;
    if (R == 1) return ((t & ~7) << 3) | (v << 3) | (t & 7);
    if (R == 2) return ((t & ~63) << 3) | (v << 6) | (t & 63);
    return (v << 9) | t;
}

// SU(2) butterfly, staged by shared multiplicand.
// g = (u00r, u00i, u01r, u01i); u10 = -conj(u01), u11 = conj(u00).
__device__ __forceinline__ void bfly(float4 g, float& r0, float& i0, float& r1, float& i1) {
    const float a = r0, b = i0, c = r1, d = i1;
    float n0 =  g.x * a;
    float n1 =  g.y * a;
    float n2 = -g.z * a;
    float n3 =  g.w * a;
    n0 = fmaf(-g.y, b, n0);
    n1 = fmaf( g.x, b, n1);
    n2 = fmaf(-g.w, b, n2);
    n3 = fmaf(-g.z, b, n3);
    n0 = fmaf( g.z, c, n0);
    n1 = fmaf( g.w, c, n1);
    n2 = fmaf( g.x, c, n2);
    n3 = fmaf(-g.y, c, n3);
    n0 = fmaf(-g.w, d, n0);
    n1 = fmaf( g.z, d, n1);
    n2 = fmaf( g.y, d, n2);
    n3 = fmaf( g.x, d, n3);
    r0 = n0; i0 = n1; r1 = n2; i1 = n3;
}

// gather 8 amps; apply this round's 3 gates in registers
template <int R>
__device__ __forceinline__ void gather_apply(const float2* __restrict__ st,
                                             const float4* __restrict__ Ug,
                                             int L, int t,
                                             float* re, float* im) {
    #pragma unroll
    for (int v = 0; v < PER; ++v) {
        const float2 a = st[saddr(jidx<R>(t, v))];
        re[v] = a.x; im[v] = a.y;
    }
    #pragma unroll
    for (int lb = 0; lb < 3; ++lb) {
        const int wi = 11 - (3 * R + lb);
        const float4 g = Ug[L * NWIRES + wi];
        const int str = 1 << lb;
        #pragma unroll
        for (int p = 0; p < 4; ++p) {
            const int i0 = ((p & ~(str - 1)) << 1) | (p & (str - 1));
            const int i1 = i0 | str;
            bfly(g, re[i0], im[i0], re[i1], im[i1]);
        }
    }
}

// scatter to own slots (read-set == write-set per thread: race-free)
template <int R>
__device__ __forceinline__ void scatter(float2* __restrict__ st, int t,
                                        const float* re, const float* im) {
    #pragma unroll
    for (int v = 0; v < PER; ++v)
        st[saddr(jidx<R>(t, v))] = make_float2(re[v], im[v]);
}

__global__ __launch_bounds__(NT, 3)
void qnn_kernel(const float* __restrict__ x, const float* __restrict__ w,
                float* __restrict__ out)
{
    __shared__ float2 st[DIM];                    // 32 KB state (swizzled)
    __shared__ float4 Ug[NLAYERS * NWIRES];       // SU(2) gates: 1 float4 each
    __shared__ float  red[16 * 8];                // 16 warps x 8 outputs

    const int b = blockIdx.x;
    const int t = threadIdx.x;

    // ---- build fused SU(2) gates U = RZ RY RX @ Enc (48 threads) ----
    if (t < NLAYERS * NWIRES) {
        const int l = t / NWIRES, wi = t % NWIRES;
        const float* wp = w + (l * NWIRES + wi) * 3;
        float sa, ca, sb, cb, sg, cg;
        sincosf(0.5f * wp[0], &sa, &ca);
        sincosf(0.5f * wp[1], &sb, &cb);
        sincosf(0.5f * wp[2], &sg, &cg);
        float2 m00 = make_float2( cb * ca,  sb * sa);
        float2 m01 = make_float2(-sb * ca, -cb * sa);
        const float2 e0 = make_float2(cg, -sg);
        m00 = cmul(e0, m00); m01 = cmul(e0, m01);
        const float th = x[b * 2 + (wi & 1)];
        float se, ce;
        sincosf(0.5f * th, &se, &ce);
        float2 E00, E01, E10, E11;
        if (wi & 1) { // RY
            E00 = make_float2(ce, 0.f);  E01 = make_float2(-se, 0.f);
            E10 = make_float2(se, 0.f);  E11 = make_float2(ce, 0.f);
        } else {      // RX
            E00 = make_float2(ce, 0.f);  E01 = make_float2(0.f, -se);
            E10 = make_float2(0.f, -se); E11 = make_float2(ce, 0.f);
        }
        const float2 u00 = cfma(m01, E10, cmul(m00, E00));
        const float2 u01 = cfma(m01, E11, cmul(m00, E01));
        Ug[t] = make_float4(u00.x, u00.y, u01.x, u01.y);
    }
    __syncthreads();

    // ---- layer 0 on |0..0>: product state, stored through CNOT map h ----
    // (writes only; no prior reader of st -> no WAR hazard here)
    {
        float pre = 1.f, pim = 0.f;
        #pragma unroll
        for (int bit = 0; bit < 9; ++bit) {           // t covers bits 0-8 (wires 11..3)
            const int row = (t >> bit) & 1;
            const float4 g = Ug[11 - bit];
            const float cr = row ? -g.z : g.x;
            const float ci = row ?  g.w : g.y;
            const float nre = fmaf(cr, pre, -(ci * pim));
            const float nim = fmaf(ci, pre,   cr * pim);
            pre = nre; pim = nim;
        }
        #pragma unroll
        for (int v = 0; v < PER; ++v) {               // v covers bits 9-11 (wires 2..0)
            float vre = pre, vim = pim;
            #pragma unroll
            for (int bit = 0; bit < 3; ++bit) {
                const int row = (v >> bit) & 1;
                const float4 g = Ug[2 - bit];
                const float cr = row ? -g.z : g.x;
                const float ci = row ?  g.w : g.y;
                const float nre = fmaf(cr, vre, -(ci * vim));
                const float nim = fmaf(ci, vre,   cr * vim);
                vre = nre; vim = nim;
            }
            st[haddr((v << 9) | t)] = make_float2(vre, vim);
        }
    }
    __syncthreads();

    float re[PER], im[PER];

    // ---- layers 1..2: 4 rounds each, last round scatters through h ----
    #pragma unroll 1
    for (int L = 1; L <= 2; ++L) {
        gather_apply<0>(st, Ug, L, t, re, im);
        scatter<0>(st, t, re, im);
        __syncthreads();
        gather_apply<1>(st, Ug, L, t, re, im);
        scatter<1>(st, t, re, im);
        __syncthreads();
        gather_apply<2>(st, Ug, L, t, re, im);
        scatter<2>(st, t, re, im);
        __syncthreads();
        gather_apply<3>(st, Ug, L, t, re, im);
        __syncthreads();   // RACE FIX: h-scatter targets OTHER threads' read slots;
                           // all round-3 gathers must complete before any h-store
        #pragma unroll
        for (int v = 0; v < PER; ++v)
            st[haddr((v << 9) | t)] = make_float2(re[v], im[v]);
        __syncthreads();
    }

    // ---- layer 3: rounds 0-2; round 3 fused with measurement (no store) ----
    {
        gather_apply<0>(st, Ug, 3, t, re, im);
        scatter<0>(st, t, re, im);
        __syncthreads();
        gather_apply<1>(st, Ug, 3, t, re, im);
        scatter<1>(st, t, re, im);
        __syncthreads();
        gather_apply<2>(st, Ug, 3, t, re, im);
        scatter<2>(st, t, re, im);
        __syncthreads();
        gather_apply<3>(st, Ug, 3, t, re, im);
    }

    // ---- measurement straight from registers ----
    // slot v = pre-chain logical bits 9-11; post-chain m = h(j):
    //   wire0 = v2 ; wire1 = v1^v2 ; wire2 = v0^v1^v2
    //   wire k (3..7): sign = (t8^..^t_{12-k}) ^ (v0^v1^v2)
    float acc0 = 0.f, acc1 = 0.f, acc2 = 0.f;
    #pragma unroll
    for (int v = 0; v < PER; ++v) {
        const float p = fmaf(re[v], re[v], im[v] * im[v]);
        const int v2 = (v >> 2) & 1, v1 = (v >> 1) & 1, v0 = v & 1;
        acc0 += v2 ? -p : p;
        acc1 += (v2 ^ v1) ? -p : p;
        acc2 += (v2 ^ v1 ^ v0) ? -p : p;
    }
    const int t8 = (t >> 8) & 1, t7 = (t >> 7) & 1, t6 = (t >> 6) & 1,
              t5 = (t >> 5) & 1, t4 = (t >> 4) & 1;
    float rr[8];
    rr[0] = acc0; rr[1] = acc1; rr[2] = acc2;
    rr[3] = t8 ? -acc2 : acc2;
    rr[4] = (t8 ^ t7) ? -acc2 : acc2;
    rr[5] = (t8 ^ t7 ^ t6) ? -acc2 : acc2;
    rr[6] = (t8 ^ t7 ^ t6 ^ t5) ? -acc2 : acc2;
    rr[7] = (t8 ^ t7 ^ t6 ^ t5 ^ t4) ? -acc2 : acc2;

    const unsigned FULL = 0xffffffffu;
    #pragma unroll
    for (int i = 0; i < 8; ++i) {
        float v = rr[i];
        #pragma unroll
        for (int o = 16; o > 0; o >>= 1) v += __shfl_xor_sync(FULL, v, o);
        if ((t & 31) == 0) red[(t >> 5) * 8 + i] = v;
    }
    __syncthreads();
    if (t < 8) {
        float s = 0.f;
        #pragma unroll
        for (int wp2 = 0; wp2 < 16; ++wp2) s += red[wp2 * 8 + t];
        out[b * 8 + t] = s * 3.14159265358979f;
    }
}

extern "C" void kernel_launch(void* const* d_in, const int* in_sizes, int n_in,
                              void* d_out, int out_size) {
    const float* x = (const float*)d_in[0];   // [B, 2]
    const float* w = (const float*)d_in[1];   // [4, 12, 3]
    float* out = (float*)d_out;               // [B, 8]
    const int B = in_sizes[0] / 2;
    qnn_kernel<<<B, NT>>>(x, w, out);
}

// round 11
// speedup vs baseline: 1.1711x; 1.1711x over previous
#include <cuda_runtime.h>

#define NWIRES  12
#define DIM     4096
#define NLAYERS 4
#define NT      256

__device__ __forceinline__ float2 cmul(float2 a, float2 b) {
    return make_float2(fmaf(a.x, b.x, -(a.y * b.y)),
                       fmaf(a.x, b.y,   a.y * b.x));
}

// bank-conflict-avoiding swizzle: XOR low 4 bits with bits 4-7 (GF(2)-linear)
__device__ __forceinline__ int saddr(int j) { return j ^ ((j >> 4) & 15); }
// h = g^{-1} (prefix-XOR) of the CNOT-chain permutation (GF(2)-linear)
__device__ __forceinline__ int hperm(int j) {
    j ^= j >> 1; j ^= j >> 2; j ^= j >> 4; j ^= j >> 8;
    return j;
}
__device__ __forceinline__ int haddr(int j) { return saddr(hperm(j)); }

// XOR-base addressing: slot address = abase<R>(t) ^ aoff<R>(v), aoff compile-time
template <int R> __device__ __forceinline__ int abase(int t) {
    if (R == 0) return (t << 4) ^ (t & 15);
    if (R == 1) return ((t & 0xF0) << 4) | (t & 15);
    return t ^ ((t >> 4) & 15);
}
template <int R> __device__ __forceinline__ int aoff(int v) {
    if (R == 0) return v;
    if (R == 1) return v * 17;      // (v<<4)|v
    return v << 8;
}

// SU(2) butterfly, staged by shared multiplicand.
// g = (u00r, u00i, u01r, u01i); u10 = -conj(u01), u11 = conj(u00).
__device__ __forceinline__ void bfly(float4 g, float& r0, float& i0, float& r1, float& i1) {
    const float a = r0, b = i0, c = r1, d = i1;
    float n0 =  g.x * a;
    float n1 =  g.y * a;
    float n2 = -g.z * a;
    float n3 =  g.w * a;
    n0 = fmaf(-g.y, b, n0);
    n1 = fmaf( g.x, b, n1);
    n2 = fmaf(-g.w, b, n2);
    n3 = fmaf(-g.z, b, n3);
    n0 = fmaf( g.z, c, n0);
    n1 = fmaf( g.w, c, n1);
    n2 = fmaf( g.x, c, n2);
    n3 = fmaf(-g.y, c, n3);
    n0 = fmaf(-g.w, d, n0);
    n1 = fmaf( g.z, d, n1);
    n2 = fmaf( g.y, d, n2);
    n3 = fmaf( g.x, d, n3);
    r0 = n0; i0 = n1; r1 = n2; i1 = n3;
}

// gather 16 amps; apply round R's 4 gates (layer L compile-time)
template <int L, int R>
__device__ __forceinline__ void gather_apply(const float2* __restrict__ st,
                                             const float4* __restrict__ Ug,
                                             int t, float* re, float* im) {
    const int base = abase<R>(t);
    #pragma unroll
    for (int v = 0; v < 16; ++v) {
        const float2 a = st[base ^ aoff<R>(v)];
        re[v] = a.x; im[v] = a.y;
    }
    #pragma unroll
    for (int lb = 0; lb < 4; ++lb) {
        const float4 g = Ug[L * NWIRES + (11 - (4 * R + lb))];
        const int str = 1 << lb;
        #pragma unroll
        for (int p = 0; p < 8; ++p) {
            const int i0 = ((p & ~(str - 1)) << 1) | (p & (str - 1));
            const int i1 = i0 | str;
            bfly(g, re[i0], im[i0], re[i1], im[i1]);
        }
    }
}

// scatter to own slots (read-set == write-set per thread: race-free)
template <int R>
__device__ __forceinline__ void scatter(float2* __restrict__ st, int t,
                                        const float* re, const float* im) {
    const int base = abase<R>(t);
    #pragma unroll
    for (int v = 0; v < 16; ++v)
        st[base ^ aoff<R>(v)] = make_float2(re[v], im[v]);
}

__global__ __launch_bounds__(NT, 3)
void qnn_kernel(const float* __restrict__ x, const float* __restrict__ w,
                float* __restrict__ out)
{
    __shared__ float2 st[DIM];                    // 32 KB state (swizzled)
    __shared__ float4 Ug[NLAYERS * NWIRES];       // SU(2) gates: 1 float4 each
    __shared__ float2 sc[146];                    // sincos staging: 144 weight + 2 enc
    __shared__ float  red[8 * 8];

    const int b = blockIdx.x;
    const int t = threadIdx.x;

    // ---- parallel sincos: one per thread ----
    if (t < 144) {
        float s, c;
        sincosf(0.5f * w[t], &s, &c);
        sc[t] = make_float2(c, s);
    } else if (t < 146) {
        float s, c;
        sincosf(0.5f * x[b * 2 + (t - 144)], &s, &c);
        sc[t] = make_float2(c, s);
    }
    __syncthreads();

    // ---- assemble fused SU(2) gates U = RZ RY RX @ Enc (48 threads) ----
    if (t < NLAYERS * NWIRES) {
        const int wi = t % NWIRES;
        const float2 A = sc[t * 3 + 0];   // (ca, sa) for RX angle
        const float2 Bc = sc[t * 3 + 1];  // (cb, sb) for RY angle
        const float2 G = sc[t * 3 + 2];   // (cg, sg) for RZ angle
        float2 m00 = make_float2( Bc.x * A.x,  Bc.y * A.y);
        float2 m01 = make_float2(-Bc.y * A.x, -Bc.x * A.y);
        const float2 e0 = make_float2(G.x, -G.y);
        m00 = cmul(e0, m00); m01 = cmul(e0, m01);
        const float2 E = sc[144 + (wi & 1)];     // (ce, se)
        float2 u00, u01;
        if (wi & 1) { // RY encoding: E10 = (se,0), E00 = (ce,0), E01 = (-se,0), E11 = (ce,0)
            u00 = make_float2(fmaf(m00.x, E.x,  m01.x * E.y),
                              fmaf(m00.y, E.x,  m01.y * E.y));
            u01 = make_float2(fmaf(m00.x, -E.y, m01.x * E.x),
                              fmaf(m00.y, -E.y, m01.y * E.x));
        } else {      // RX encoding: E00 = (ce,0), E01 = E10 = (0,-se), E11 = (ce,0)
            // u00 = m00*ce + m01*(0,-se) ; u01 = m00*(0,-se) + m01*ce
            u00 = make_float2(fmaf(m00.x, E.x,  m01.y * E.y),
                              fmaf(m00.y, E.x, -(m01.x * E.y)));
            u01 = make_float2(fmaf(m01.x, E.x,  m00.y * E.y),
                              fmaf(m01.y, E.x, -(m00.x * E.y)));
        }
        Ug[t] = make_float4(u00.x, u00.y, u01.x, u01.y);
    }
    __syncthreads();

    const int hb = haddr(t);   // runtime part of the h-scatter address

    // ---- layer 0 on |0..0>: product state via tensor tree, stored through h ----
    {
        float2 pt = make_float2(1.f, 0.f);
        #pragma unroll
        for (int bit = 0; bit < 8; ++bit) {       // t covers bits 0-7 (wires 11..4)
            const int row = (t >> bit) & 1;
            const float4 g = Ug[11 - bit];
            const float cr = row ? -g.z : g.x;    // column 0 of U
            const float ci = row ?  g.w : g.y;
            pt = cmul(make_float2(cr, ci), pt);
        }
        // v bits 0-3 = j bits 8-11 = wires 3,2,1,0
        float2 e3[2], e2[2], e1[2], e0c[2];
        {
            const float4 g3 = Ug[3], g2 = Ug[2], g1 = Ug[1], g0 = Ug[0];
            e3[0] = make_float2(g3.x, g3.y);  e3[1] = make_float2(-g3.z, g3.w);
            e2[0] = make_float2(g2.x, g2.y);  e2[1] = make_float2(-g2.z, g2.w);
            e1[0] = make_float2(g1.x, g1.y);  e1[1] = make_float2(-g1.z, g1.w);
            e0c[0] = make_float2(g0.x, g0.y); e0c[1] = make_float2(-g0.z, g0.w);
        }
        float2 PA[4], PB[4];
        #pragma unroll
        for (int a = 0; a < 4; ++a)
            PA[a] = cmul(cmul(e3[a & 1], e2[(a >> 1) & 1]), pt);
        #pragma unroll
        for (int bb = 0; bb < 4; ++bb)
            PB[bb] = cmul(e1[bb & 1], e0c[(bb >> 1) & 1]);
        #pragma unroll
        for (int v = 0; v < 16; ++v)
            st[hb ^ haddr(v << 8)] = cmul(PA[v & 3], PB[v >> 2]);
    }
    __syncthreads();

    float re[16], im[16];

    // ---- layers 1..2 (compile-time unrolled); h-scatter behind a barrier ----
    #define DO_LAYER(L)                                                        \
        gather_apply<L, 0>(st, Ug, t, re, im);                                 \
        scatter<0>(st, t, re, im);                                             \
        __syncwarp();                       /* round0<->round1: warp-local */  \
        gather_apply<L, 1>(st, Ug, t, re, im);                                 \
        scatter<1>(st, t, re, im);                                             \
        __syncthreads();                                                       \
        gather_apply<L, 2>(st, Ug, t, re, im);                                 \
        __syncthreads();                    /* RACE FIX: h targets others */   \
        _Pragma("unroll")                                                      \
        for (int v = 0; v < 16; ++v)                                           \
            st[hb ^ haddr(v << 8)] = make_float2(re[v], im[v]);                \
        __syncthreads();

    DO_LAYER(1)
    DO_LAYER(2)

    // ---- layer 3: rounds 0,1; round 2 fused with measurement (no store) ----
    gather_apply<3, 0>(st, Ug, t, re, im);
    scatter<0>(st, t, re, im);
    __syncwarp();
    gather_apply<3, 1>(st, Ug, t, re, im);
    scatter<1>(st, t, re, im);
    __syncthreads();
    gather_apply<3, 2>(st, Ug, t, re, im);

    // ---- measurement straight from registers ----
    // slot v = pre-chain bits 8-11; post-chain sign wire0=v3, wire1=v3^v2,
    // wire2=v3^v2^v1, wire3=parity(v); wires 4-7 add t7..t4 parities.
    float acc0 = 0.f, acc1 = 0.f, acc2 = 0.f, dpar = 0.f;
    #pragma unroll
    for (int v = 0; v < 16; ++v) {
        const float p = fmaf(re[v], re[v], im[v] * im[v]);
        const int v3 = (v >> 3) & 1, v2 = (v >> 2) & 1, v1 = (v >> 1) & 1, v0 = v & 1;
        acc0 += v3 ? -p : p;
        acc1 += (v3 ^ v2) ? -p : p;
        acc2 += (v3 ^ v2 ^ v1) ? -p : p;
        dpar += (v3 ^ v2 ^ v1 ^ v0) ? -p : p;
    }
    const int t4 = (t >> 4) & 1;
    float d4 = t4 ? -dpar : dpar;

    // 5 warp reductions; warp-uniform signs applied at leader write
    const unsigned FULL = 0xffffffffu;
    float vals[5] = {acc0, acc1, acc2, dpar, d4};
    #pragma unroll
    for (int i = 0; i < 5; ++i) {
        float v = vals[i];
        #pragma unroll
        for (int o = 16; o > 0; o >>= 1) v += __shfl_xor_sync(FULL, v, o);
        vals[i] = v;
    }
    if ((t & 31) == 0) {
        const int wp = t >> 5;
        const int t7 = (t >> 7) & 1, t6 = (t >> 6) & 1, t5 = (t >> 5) & 1;
        const float D = vals[3], D4 = vals[4];
        red[wp * 8 + 0] = vals[0];
        red[wp * 8 + 1] = vals[1];
        red[wp * 8 + 2] = vals[2];
        red[wp * 8 + 3] = D;
        red[wp * 8 + 4] = t7 ? -D : D;
        red[wp * 8 + 5] = (t7 ^ t6) ? -D : D;
        red[wp * 8 + 6] = (t7 ^ t6 ^ t5) ? -D : D;
        red[wp * 8 + 7] = (t7 ^ t6 ^ t5) ? -D4 : D4;   // t4 sign already in D4
    }
    __syncthreads();
    if (t < 8) {
        float s = 0.f;
        #pragma unroll
        for (int wp2 = 0; wp2 < 8; ++wp2) s += red[wp2 * 8 + t];
        out[b * 8 + t] = s * 3.14159265358979f;
    }
}

extern "C" void kernel_launch(void* const* d_in, const int* in_sizes, int n_in,
                              void* d_out, int out_size) {
    const float* x = (const float*)d_in[0];   // [B, 2]
    const float* w = (const float*)d_in[1];   // [4, 12, 3]
    float* out = (float*)d_out;               // [B, 8]
    const int B = in_sizes[0] / 2;
    qnn_kernel<<<B, NT>>>(x, w, out);
}